// round 4
// baseline (speedup 1.0000x reference)
#include <cuda_runtime.h>
#include <cstdint>

#define BB 64
#define TT 512
#define DD 256
#define UU 512
#define NCTA 128
#define WROW 520          // weight row stride (floats)
#define HROWF 516         // padded h row (floats): 2064 B == 16 mod 128 -> conflict-free
#define HROWB 2064
#define HBYTES (64 * HROWB)        // 132096
#define NCH 8
#define CHUNK (HBYTES / NCH)       // 16512 (8 rows)

// dynamic smem layout for lstm kernel
#define W_OFF    HBYTES                          // 132096
#define W_BYTES  (3 * 4 * WROW * 4)              // 24960
#define R_OFF    (W_OFF + W_BYTES)               // 157056
#define R_BYTES  (2 * 3 * 64 * 5 * 4)            // 7680
#define MBAR_OFF (R_OFF + R_BYTES)               // 164736
#define SM_TOTAL (MBAR_OFF + NCH * 8)            // 164800

// Scratch (static device arrays; no cudaMalloc anywhere).
__device__ float g_xp[3][TT][BB][UU];      // input projections [g][t][b][u]
__device__ float g_hbuf[2][64 * HROWF];    // ping-pong hidden state, padded rows
__device__ unsigned g_count;               // grid barrier counter

// ---- packed f32x2 helpers (full-rate fp32 on sm_103a) ----
__device__ __forceinline__ void fma2(unsigned long long &d, unsigned long long a,
                                     unsigned long long b) {
    asm("fma.rn.f32x2 %0, %1, %2, %0;" : "+l"(d) : "l"(a), "l"(b));
}
__device__ __forceinline__ float2 upk(unsigned long long v) {
    float2 r;
    asm("mov.b64 {%0, %1}, %2;" : "=f"(r.x), "=f"(r.y) : "l"(v));
    return r;
}

__device__ __forceinline__ float fsig(float x) {
    return __fdividef(1.0f, 1.0f + __expf(-x));
}
__device__ __forceinline__ float ftanh(float x) {
    float e = __expf(-2.0f * fabsf(x));
    float r = __fdividef(1.0f - e, 1.0f + e);
    return copysignf(r, x);
}

// ============================================================================
// Phase 1: xp[g][t][b][u] = x[b,t,:] @ w_xg[:,u] + b_g[u]   (unchanged)
// ============================================================================
__global__ void __launch_bounds__(256, 2) proj_kernel(
    const float* __restrict__ x,
    const float* __restrict__ wxi, const float* __restrict__ wxf,
    const float* __restrict__ wxc,
    const float* __restrict__ bi, const float* __restrict__ bf,
    const float* __restrict__ bc) {
    __shared__ __align__(16) float xs[64][33];
    __shared__ __align__(16) float ws[3][32][64];

    const int tid = threadIdx.x;
    const int t = blockIdx.y;
    const int ub = blockIdx.x * 64;

    if (blockIdx.x == 0 && blockIdx.y == 0 && tid == 0) g_count = 0u;

    const int ug = tid & 15;
    const int bg = tid >> 4;
    const int ul = ug << 2;
    const int b0 = bg << 2;

    unsigned long long acc[3][4][2];
#pragma unroll
    for (int g = 0; g < 3; ++g)
#pragma unroll
        for (int i = 0; i < 4; ++i) { acc[g][i][0] = 0ull; acc[g][i][1] = 0ull; }

    for (int k0 = 0; k0 < DD; k0 += 32) {
#pragma unroll
        for (int i = 0; i < 8; ++i) {
            int idx = tid + i * 256;
            int bb = idx >> 5, kk = idx & 31;
            xs[bb][kk] = x[(bb * TT + t) * DD + k0 + kk];
        }
#pragma unroll
        for (int i = 0; i < 24; ++i) {
            int idx = tid + i * 256;
            int g = idx >> 11, r = idx & 2047, kk = r >> 6, uu = r & 63;
            const float* w = (g == 0) ? wxi : ((g == 1) ? wxf : wxc);
            ws[g][kk][uu] = w[(k0 + kk) * UU + ub + uu];
        }
        __syncthreads();
#pragma unroll
        for (int kk = 0; kk < 32; ++kk) {
            unsigned long long xb[4];
#pragma unroll
            for (int i = 0; i < 4; ++i) {
                unsigned xv = __float_as_uint(xs[b0 + i][kk]);
                asm("mov.b64 %0, {%1, %1};" : "=l"(xb[i]) : "r"(xv));
            }
#pragma unroll
            for (int g = 0; g < 3; ++g) {
                const ulonglong2 wv = *(const ulonglong2*)&ws[g][kk][ul];
#pragma unroll
                for (int i = 0; i < 4; ++i) {
                    fma2(acc[g][i][0], xb[i], wv.x);
                    fma2(acc[g][i][1], xb[i], wv.y);
                }
            }
        }
        __syncthreads();
    }

    const float* biases[3] = {bi, bf, bc};
#pragma unroll
    for (int g = 0; g < 3; ++g) {
        float2 bv0 = *(const float2*)&biases[g][ub + ul];
        float2 bv1 = *(const float2*)&biases[g][ub + ul + 2];
#pragma unroll
        for (int i = 0; i < 4; ++i) {
            float2 r0 = upk(acc[g][i][0]);
            float2 r1 = upk(acc[g][i][1]);
            r0.x += bv0.x; r0.y += bv0.y;
            r1.x += bv1.x; r1.y += bv1.y;
            float* dst = &g_xp[g][t][b0 + i][ub + ul];
            *(float2*)dst = r0;
            *(float2*)(dst + 2) = r1;
        }
    }
}

// ============================================================================
// Init: re-pad h0 [64][512] -> g_hbuf[1] [64][516]
// ============================================================================
__global__ void init_kernel(const float* __restrict__ h0) {
    int r = blockIdx.x;
    for (int u = threadIdx.x; u < UU; u += blockDim.x)
        g_hbuf[1][r * HROWF + u] = h0[r * UU + u];
}

// ============================================================================
// Phase 2: persistent recurrent kernel. 128 CTAs x 512 threads.
// CTA owns 4 U-columns x 3 gates. h staged via cp.async.bulk in 8 row-chunks
// with per-chunk mbarriers; warp (q,s0,s1): chunk m=2q+s0, k-half kh=s1.
// Thread: row = m*8 + (lane>>2), col c = lane&3; 64 k4 x 3 gates.
// Gate phase (tid<256): b=tid>>2, c=tid&3 owns cell state in a register.
// ============================================================================
__global__ void __launch_bounds__(512, 1) lstm_kernel(
    const float* __restrict__ whi, const float* __restrict__ whf,
    const float* __restrict__ whc, const float* __restrict__ c0,
    float* __restrict__ out) {
    extern __shared__ __align__(16) char sm[];
    float* smW = (float*)(sm + W_OFF);
    float* smR = (float*)(sm + R_OFF);

    const int tid = threadIdx.x;
    const int w = tid >> 5, lane = tid & 31;
    const int c = lane & 3, lr = lane >> 2;
    const int m = ((w >> 2) << 1) | (w & 1);   // chunk 0..7
    const int kh = (w >> 1) & 1;               // k-half
    const int row = m * 8 + lr;                // b-row this thread computes
    const int u0 = blockIdx.x * 4;
    const int b2 = tid >> 2, c2 = tid & 3;     // gate roles (tid<256)
    const int u = u0 + c2;

    {
        const float* wsrc[3] = {whi, whf, whc};
        for (int i = tid; i < 3 * 4 * UU; i += 512) {
            int cc = i & 3, k = (i >> 2) & 511, g = i >> 11;
            smW[(g * 4 + cc) * WROW + k] = wsrc[g][k * UU + u0 + cc];
        }
    }
    float cst = (tid < 256) ? c0[b2 * UU + u] : 0.0f;

    const uint32_t smbase = (uint32_t)__cvta_generic_to_shared(sm);
    const uint32_t mb0 = smbase + MBAR_OFF;
    if (tid == 0) {
#pragma unroll
        for (int i = 0; i < NCH; ++i)
            asm volatile("mbarrier.init.shared.b64 [%0], 1;" :: "r"(mb0 + 8 * i)
                         : "memory");
    }
    __syncthreads();

    const float* wp0 = smW + (0 * 4 + c) * WROW + kh * 256;
    const float* wp1 = smW + (1 * 4 + c) * WROW + kh * 256;
    const float* wp2 = smW + (2 * 4 + c) * WROW + kh * 256;
    const char* hbase = sm + row * HROWB + kh * 1024;
    float* redw = smR + ((kh * 3) * 64 + row) * 5 + c;   // + g*320
    const float* redr = smR + b2 * 5 + c2;               // + (kh*3+g)*320
    const uint32_t mymb = mb0 + 8 * m;

    const float* xpbase = &g_xp[0][0][0][0];
    const size_t gstride = (size_t)TT * BB * UU;
    const float* xpi = xpbase + 0 * gstride + (size_t)b2 * UU + u;
    const float* xpf = xpbase + 1 * gstride + (size_t)b2 * UU + u;
    const float* xpc = xpbase + 2 * gstride + (size_t)b2 * UU + u;
    float* orow = out + (size_t)b2 * TT * UU + u;

    for (int t = 0; t < TT; ++t) {
        float pi = 0.f, pf = 0.f, pc = 0.f;
        if (tid < 256) {
            pi = __ldcg(xpi + (size_t)t * (BB * UU));
            pf = __ldcg(xpf + (size_t)t * (BB * UU));
            pc = __ldcg(xpc + (size_t)t * (BB * UU));
        }

        if (tid == 0) {
            asm volatile("fence.proxy.async.shared::cta;" ::: "memory");
            const float* hsrc = &g_hbuf[(t + 1) & 1][0];
#pragma unroll
            for (int i = 0; i < NCH; ++i) {
                uint32_t bar = mb0 + 8 * i;
                asm volatile(
                    "mbarrier.arrive.expect_tx.shared.b64 _, [%0], %1;"
                    :: "r"(bar), "r"((unsigned)CHUNK) : "memory");
                asm volatile(
                    "cp.async.bulk.shared::cluster.global.mbarrier::complete_tx::bytes "
                    "[%0], [%1], %2, [%3];"
                    :: "r"(smbase + i * CHUNK), "l"(hsrc + i * (CHUNK / 4)),
                       "r"((unsigned)CHUNK), "r"(bar) : "memory");
            }
        }

        // wait for this warp's chunk
        asm volatile(
            "{\n\t.reg .pred p;\n\t"
            "WL%=:\n\t"
            "mbarrier.try_wait.parity.acquire.cta.shared::cta.b64 p, [%0], %1;\n\t"
            "@!p bra WL%=;\n\t}"
            :: "r"(mymb), "r"((unsigned)(t & 1)) : "memory");

        unsigned long long a00 = 0, a01 = 0, a10 = 0, a11 = 0, a20 = 0, a21 = 0;
#pragma unroll 16
        for (int j = 0; j < 64; ++j) {
            const ulonglong2 hv = *(const ulonglong2*)(hbase + (j << 4));
            const ulonglong2 v0 = *(const ulonglong2*)(wp0 + (j << 2));
            const ulonglong2 v1 = *(const ulonglong2*)(wp1 + (j << 2));
            const ulonglong2 v2 = *(const ulonglong2*)(wp2 + (j << 2));
            fma2(a00, hv.x, v0.x); fma2(a01, hv.y, v0.y);
            fma2(a10, hv.x, v1.x); fma2(a11, hv.y, v1.y);
            fma2(a20, hv.x, v2.x); fma2(a21, hv.y, v2.y);
        }
        {
            float2 x0 = upk(a00), y0 = upk(a01);
            redw[0]   = (x0.x + x0.y) + (y0.x + y0.y);
            float2 x1 = upk(a10), y1 = upk(a11);
            redw[320] = (x1.x + x1.y) + (y1.x + y1.y);
            float2 x2 = upk(a20), y2 = upk(a21);
            redw[640] = (x2.x + x2.y) + (y2.x + y2.y);
        }
        __syncthreads();   // all smem-h reads + red writes done

        if (tid < 256) {
            float s0 = redr[0]   + redr[960];
            float s1 = redr[320] + redr[1280];
            float s2 = redr[640] + redr[1600];
            float ig = fsig(pi + s0);
            float fg = fsig(pf + s1);
            float cin = ftanh(pc + s2);
            cst = fg * cst + ig * cin;
            float hn = ftanh(cst);
            g_hbuf[t & 1][b2 * HROWF + u] = hn;
            orow[(size_t)t * UU] = hn;
        }
        __syncthreads();

        if (t < TT - 1) {
            if (tid == 0) {
                unsigned prev;
                asm volatile("atom.add.release.gpu.u32 %0, [%1], 1;"
                             : "=r"(prev) : "l"(&g_count) : "memory");
                unsigned target = (unsigned)(t + 1) * NCTA;
                unsigned v;
                do {
                    asm volatile("ld.acquire.gpu.u32 %0, [%1];"
                                 : "=r"(v) : "l"(&g_count) : "memory");
                } while (v < target);
            }
            __syncthreads();
        }
    }
}

extern "C" void kernel_launch(void* const* d_in, const int* in_sizes, int n_in,
                              void* d_out, int out_size) {
    const float* x   = (const float*)d_in[0];
    const float* wxi = (const float*)d_in[1];
    const float* wxf = (const float*)d_in[2];
    const float* wxc = (const float*)d_in[3];
    const float* whi = (const float*)d_in[4];
    const float* whf = (const float*)d_in[5];
    const float* whc = (const float*)d_in[6];
    const float* bi  = (const float*)d_in[7];
    const float* bf  = (const float*)d_in[8];
    const float* bc  = (const float*)d_in[9];
    const float* h0  = (const float*)d_in[10];
    const float* c0  = (const float*)d_in[11];
    float* out = (float*)d_out;

    cudaFuncSetAttribute(lstm_kernel, cudaFuncAttributeMaxDynamicSharedMemorySize,
                         SM_TOTAL);

    proj_kernel<<<dim3(8, TT), 256>>>(x, wxi, wxf, wxc, bi, bf, bc);
    init_kernel<<<64, 256>>>(h0);
    lstm_kernel<<<NCTA, 512, SM_TOTAL>>>(whi, whf, whc, c0, out);
}

// round 5
// speedup vs baseline: 1.6660x; 1.6660x over previous
#include <cuda_runtime.h>
#include <cstdint>

#define BB 64
#define TT 512
#define DD 256
#define UU 512
#define NCTA 128
#define WROW 520          // weight row stride (floats): c-rows land on distinct banks

// dynamic smem layout for lstm kernel
#define H_BYTES  (64 * 2048)                     // h staging [64][512] f32, swizzled
#define W_OFF    H_BYTES                         // 131072
#define W_BYTES  (3 * 4 * WROW * 4)              // 24960
#define R_OFF    (W_OFF + W_BYTES)               // 156032
#define R_BYTES  (64 * 4 * 24 * 4)               // 24576
#define SM_TOTAL (R_OFF + R_BYTES)               // 180608

// Scratch (static device arrays; no cudaMalloc anywhere).
__device__ float g_xp[3][TT][BB][UU];      // input projections [g][t][b][u]
__device__ float g_hbuf[2][BB * UU];       // ping-pong hidden state
__device__ unsigned g_count;               // grid barrier counter

// ---- packed f32x2 helpers (full-rate fp32 on sm_103a) ----
__device__ __forceinline__ void fma2(unsigned long long &d, unsigned long long a,
                                     unsigned long long b) {
    asm("fma.rn.f32x2 %0, %1, %2, %0;" : "+l"(d) : "l"(a), "l"(b));
}
__device__ __forceinline__ float2 upk(unsigned long long v) {
    float2 r;
    asm("mov.b64 {%0, %1}, %2;" : "=f"(r.x), "=f"(r.y) : "l"(v));
    return r;
}
__device__ __forceinline__ void cp16(uint32_t dst, const float* src) {
    asm volatile("cp.async.cg.shared.global [%0], [%1], 16;" :: "r"(dst), "l"(src));
}

__device__ __forceinline__ float fsig(float x) {
    return __fdividef(1.0f, 1.0f + __expf(-x));
}
__device__ __forceinline__ float ftanh(float x) {
    float e = __expf(-2.0f * fabsf(x));
    float r = __fdividef(1.0f - e, 1.0f + e);
    return copysignf(r, x);
}

// ============================================================================
// Phase 1: xp[g][t][b][u] = x[b,t,:] @ w_xg[:,u] + b_g[u]   (unchanged)
// ============================================================================
__global__ void __launch_bounds__(256, 2) proj_kernel(
    const float* __restrict__ x,
    const float* __restrict__ wxi, const float* __restrict__ wxf,
    const float* __restrict__ wxc,
    const float* __restrict__ bi, const float* __restrict__ bf,
    const float* __restrict__ bc) {
    __shared__ __align__(16) float xs[64][33];
    __shared__ __align__(16) float ws[3][32][64];

    const int tid = threadIdx.x;
    const int t = blockIdx.y;
    const int ub = blockIdx.x * 64;

    if (blockIdx.x == 0 && blockIdx.y == 0 && tid == 0) g_count = 0u;

    const int ug = tid & 15;
    const int bg = tid >> 4;
    const int ul = ug << 2;
    const int b0 = bg << 2;

    unsigned long long acc[3][4][2];
#pragma unroll
    for (int g = 0; g < 3; ++g)
#pragma unroll
        for (int i = 0; i < 4; ++i) { acc[g][i][0] = 0ull; acc[g][i][1] = 0ull; }

    for (int k0 = 0; k0 < DD; k0 += 32) {
#pragma unroll
        for (int i = 0; i < 8; ++i) {
            int idx = tid + i * 256;
            int bb = idx >> 5, kk = idx & 31;
            xs[bb][kk] = x[(bb * TT + t) * DD + k0 + kk];
        }
#pragma unroll
        for (int i = 0; i < 24; ++i) {
            int idx = tid + i * 256;
            int g = idx >> 11, r = idx & 2047, kk = r >> 6, uu = r & 63;
            const float* w = (g == 0) ? wxi : ((g == 1) ? wxf : wxc);
            ws[g][kk][uu] = w[(k0 + kk) * UU + ub + uu];
        }
        __syncthreads();
#pragma unroll
        for (int kk = 0; kk < 32; ++kk) {
            unsigned long long xb[4];
#pragma unroll
            for (int i = 0; i < 4; ++i) {
                unsigned xv = __float_as_uint(xs[b0 + i][kk]);
                asm("mov.b64 %0, {%1, %1};" : "=l"(xb[i]) : "r"(xv));
            }
#pragma unroll
            for (int g = 0; g < 3; ++g) {
                const ulonglong2 wv = *(const ulonglong2*)&ws[g][kk][ul];
#pragma unroll
                for (int i = 0; i < 4; ++i) {
                    fma2(acc[g][i][0], xb[i], wv.x);
                    fma2(acc[g][i][1], xb[i], wv.y);
                }
            }
        }
        __syncthreads();
    }

    const float* biases[3] = {bi, bf, bc};
#pragma unroll
    for (int g = 0; g < 3; ++g) {
        float2 bv0 = *(const float2*)&biases[g][ub + ul];
        float2 bv1 = *(const float2*)&biases[g][ub + ul + 2];
#pragma unroll
        for (int i = 0; i < 4; ++i) {
            float2 r0 = upk(acc[g][i][0]);
            float2 r1 = upk(acc[g][i][1]);
            r0.x += bv0.x; r0.y += bv0.y;
            r1.x += bv1.x; r1.y += bv1.y;
            float* dst = &g_xp[g][t][b0 + i][ub + ul];
            *(float2*)dst = r0;
            *(float2*)(dst + 2) = r1;
        }
    }
}

// ============================================================================
// Init: h0 -> g_hbuf[1]
// ============================================================================
__global__ void init_kernel(const float* __restrict__ h0) {
    int i = blockIdx.x * blockDim.x + threadIdx.x;
    if (i < BB * UU) g_hbuf[1][i] = h0[i];
}

// ============================================================================
// Phase 2: persistent recurrent kernel. 128 CTAs x 512 threads.
// CTA owns 4 U-cols x 3 gates. Thread (ks=tid>>6, bg=(tid>>2)&15, c=tid&3)
// computes rows bg*4..+3 over k in [ks*64, ks*64+64).
// Warp w=(half=w&1, ks=w>>1) reads ONLY rows [32*half,+32) x slots [ks*16,+16)
// of h, and stages exactly that region itself via cp.async ->
// wait_group 0 + __syncwarp, no CTA sync before compute.
// h smem: row r at r*2048; 16B slot s stored at s ^ ((r>>2)&7)  -> 1-phase LDS.
// Partials: red[(b*4+c)*24 + g*8 + (ks ^ (bg&7))]  -> conflict-free STS;
// gate thread (b,c) sums 8 floats per gate as 2x float4 (order-agnostic).
// ============================================================================
__global__ void __launch_bounds__(512, 1) lstm_kernel(
    const float* __restrict__ whi, const float* __restrict__ whf,
    const float* __restrict__ whc, const float* __restrict__ c0,
    float* __restrict__ out) {
    extern __shared__ __align__(16) char sm[];
    float* smW = (float*)(sm + W_OFF);
    float* smR = (float*)(sm + R_OFF);

    const int tid = threadIdx.x;
    const int w = tid >> 5, lane = tid & 31;
    const int u0 = blockIdx.x * 4;
    // compute roles
    const int c  = tid & 3;
    const int bg = (tid >> 2) & 15;
    const int ks = tid >> 6;             // == w>>1
    const int bgl = bg & 7;
    // staging roles (warp-local)
    const int half = w & 1;
    const int s_slot = (w >> 1) * 16 + (lane & 15);      // fixed k-slot per lane
    const int r_base = half * 32 + (lane >> 4);          // row, += 2 per it
    // gate roles (tid < 256)
    const int b2 = tid >> 2, c2 = tid & 3;
    const int u = u0 + c2;

    {
        const float* wsrc[3] = {whi, whf, whc};
        for (int i = tid; i < 3 * 4 * UU; i += 512) {
            int cc = i & 3, k = (i >> 2) & 511, g = i >> 11;
            smW[(g * 4 + cc) * WROW + k] = wsrc[g][k * UU + u0 + cc];
        }
    }
    float cst = (tid < 256) ? c0[b2 * UU + u] : 0.0f;

    const uint32_t smbase = (uint32_t)__cvta_generic_to_shared(sm);
    const float* wp0 = smW + (0 * 4 + c) * WROW + ks * 64;
    const float* wp1 = smW + (1 * 4 + c) * WROW + ks * 64;
    const float* wp2 = smW + (2 * 4 + c) * WROW + ks * 64;
    const char* hrow = sm + (bg * 4) * 2048;             // rows bg*4..+3

    float* redw = smR + ((bg * 4) * 4 + c) * 24 + (ks ^ bgl);  // + i*96 + g*8
    const float* redr = smR + tid * 24;                         // gate base (tid<256)

    const size_t gstride = (size_t)TT * BB * UU;
    const float* xpi = &g_xp[0][0][0][0] + 0 * gstride + (size_t)b2 * UU + u;
    const float* xpf = &g_xp[0][0][0][0] + 1 * gstride + (size_t)b2 * UU + u;
    const float* xpc = &g_xp[0][0][0][0] + 2 * gstride + (size_t)b2 * UU + u;
    float* orow = out + (size_t)b2 * TT * UU + u;

    __syncthreads();

    for (int t = 0; t < TT; ++t) {
        float pi = 0.f, pf = 0.f, pc = 0.f;
        if (tid < 256) {
            pi = __ldcg(xpi + (size_t)t * (BB * UU));
            pf = __ldcg(xpf + (size_t)t * (BB * UU));
            pc = __ldcg(xpc + (size_t)t * (BB * UU));
        }

        // stage THIS warp's h region (32 rows x 16 slots, 16 cp16 per lane)
        const float* hsrc = &g_hbuf[(t + 1) & 1][0];
#pragma unroll
        for (int it = 0; it < 16; ++it) {
            int r = r_base + it * 2;
            uint32_t dst = smbase + r * 2048 +
                           (uint32_t)((s_slot ^ ((r >> 2) & 7)) << 4);
            cp16(dst, hsrc + r * 512 + s_slot * 4);
        }
        asm volatile("cp.async.commit_group;");
        asm volatile("cp.async.wait_group 0;");
        __syncwarp();

        unsigned long long acc[4][3];
#pragma unroll
        for (int i = 0; i < 4; ++i)
#pragma unroll
            for (int g = 0; g < 3; ++g) acc[i][g] = 0ull;

#pragma unroll
        for (int k4 = 0; k4 < 16; ++k4) {
            const ulonglong2 v0 = *(const ulonglong2*)(wp0 + k4 * 4);
            const ulonglong2 v1 = *(const ulonglong2*)(wp1 + k4 * 4);
            const ulonglong2 v2 = *(const ulonglong2*)(wp2 + k4 * 4);
            const uint32_t koff = (uint32_t)((ks * 16 + (k4 ^ bgl)) << 4);
#pragma unroll
            for (int i = 0; i < 4; ++i) {
                const ulonglong2 hv = *(const ulonglong2*)(hrow + i * 2048 + koff);
                fma2(acc[i][0], hv.x, v0.x);
                fma2(acc[i][1], hv.x, v1.x);
                fma2(acc[i][2], hv.x, v2.x);
                fma2(acc[i][0], hv.y, v0.y);
                fma2(acc[i][1], hv.y, v1.y);
                fma2(acc[i][2], hv.y, v2.y);
            }
        }

        // conflict-free partial writes
#pragma unroll
        for (int i = 0; i < 4; ++i)
#pragma unroll
            for (int g = 0; g < 3; ++g) {
                float2 v = upk(acc[i][g]);
                redw[i * 96 + g * 8] = v.x + v.y;
            }
        __syncthreads();

        if (tid < 256) {
            float s[3];
#pragma unroll
            for (int g = 0; g < 3; ++g) {
                float4 a = *(const float4*)(redr + g * 8);
                float4 b = *(const float4*)(redr + g * 8 + 4);
                s[g] = ((a.x + a.y) + (a.z + a.w)) + ((b.x + b.y) + (b.z + b.w));
            }
            float ig = fsig(pi + s[0]);
            float fg = fsig(pf + s[1]);
            float cin = ftanh(pc + s[2]);
            cst = fg * cst + ig * cin;
            float hn = ftanh(cst);
            g_hbuf[t & 1][b2 * UU + u] = hn;
            orow[(size_t)t * UU] = hn;
        }
        __syncthreads();

        if (t < TT - 1) {
            if (tid == 511) {            // highest warp: arbiter priority
                unsigned prev;
                asm volatile("atom.add.release.gpu.u32 %0, [%1], 1;"
                             : "=r"(prev) : "l"(&g_count) : "memory");
                unsigned target = (unsigned)(t + 1) * NCTA;
                unsigned v;
                do {
                    asm volatile("ld.acquire.gpu.u32 %0, [%1];"
                                 : "=r"(v) : "l"(&g_count) : "memory");
                } while (v < target);
            }
            __syncthreads();
        }
    }
}

extern "C" void kernel_launch(void* const* d_in, const int* in_sizes, int n_in,
                              void* d_out, int out_size) {
    const float* x   = (const float*)d_in[0];
    const float* wxi = (const float*)d_in[1];
    const float* wxf = (const float*)d_in[2];
    const float* wxc = (const float*)d_in[3];
    const float* whi = (const float*)d_in[4];
    const float* whf = (const float*)d_in[5];
    const float* whc = (const float*)d_in[6];
    const float* bi  = (const float*)d_in[7];
    const float* bf  = (const float*)d_in[8];
    const float* bc  = (const float*)d_in[9];
    const float* h0  = (const float*)d_in[10];
    const float* c0  = (const float*)d_in[11];
    float* out = (float*)d_out;

    cudaFuncSetAttribute(lstm_kernel, cudaFuncAttributeMaxDynamicSharedMemorySize,
                         SM_TOTAL);

    proj_kernel<<<dim3(8, TT), 256>>>(x, wxi, wxf, wxc, bi, bf, bc);
    init_kernel<<<(BB * UU + 255) / 256, 256>>>(h0);
    lstm_kernel<<<NCTA, 512, SM_TOTAL>>>(whi, whf, whc, c0, out);
}